// round 9
// baseline (speedup 1.0000x reference)
#include <cuda_runtime.h>
#include <math.h>

// Problem shape (fixed by the dataset)
#define SEQ   2048
#define DIM   128
#define QT    64      // query rows per block
#define KT1   128     // key cols per tile in scores kernel
#define KT2   64      // key cols per tile in context kernel
#define PADK  129     // padded row stride for Q/K smem tiles (conflict-free)
#define PADP  65      // padded row stride for P smem tile
#define MAXB  32

// Softmax stats scratch: per row {max, sumexp}. Device global = allowed scratch.
__device__ float g_stats[MAXB * SEQ * 2];

// ---------------------------------------------------------------------------
// Kernel 1: raw scaled scores -> attn buffer (as scratch) + online (m, l)
// Block: 256 threads = 16(tx) x 16(ty). Thread owns rows ty+16i (i<4),
// cols tx+16j (j<8) of a 64x128 score tile.
// ---------------------------------------------------------------------------
__global__ void __launch_bounds__(256, 2) k_scores(
    const float* __restrict__ Q, const float* __restrict__ K,
    float* __restrict__ attn)
{
    extern __shared__ float sm[];
    float* sQ = sm;                  // QT  * PADK
    float* sK = sm + QT * PADK;      // KT1 * PADK

    const int b   = blockIdx.y;
    const int q0  = blockIdx.x * QT;
    const int tid = threadIdx.x;
    const int tx  = tid & 15;
    const int ty  = tid >> 4;

    // Load Q tile (64x128), float4 gmem reads, scalar smem writes (pad 129)
    const float* qg = Q + ((size_t)b * SEQ + q0) * DIM;
    for (int idx = tid * 4; idx < QT * DIM; idx += 1024) {
        int r = idx >> 7, d = idx & 127;
        float4 v = *reinterpret_cast<const float4*>(qg + idx);
        float* p = sQ + r * PADK + d;
        p[0] = v.x; p[1] = v.y; p[2] = v.z; p[3] = v.w;
    }

    float m_run[4], l_run[4];
    #pragma unroll
    for (int i = 0; i < 4; i++) { m_run[i] = -1e30f; l_run[i] = 0.f; }

    const float scale = 0.08838834764831845f;  // 1/sqrt(128)

    for (int k0 = 0; k0 < SEQ; k0 += KT1) {
        __syncthreads();  // protect previous sK reads (and first-iter sQ writes)
        const float* kg = K + ((size_t)b * SEQ + k0) * DIM;
        for (int idx = tid * 4; idx < KT1 * DIM; idx += 1024) {
            int r = idx >> 7, d = idx & 127;
            float4 v = *reinterpret_cast<const float4*>(kg + idx);
            float* p = sK + r * PADK + d;
            p[0] = v.x; p[1] = v.y; p[2] = v.z; p[3] = v.w;
        }
        __syncthreads();

        float acc[4][8];
        #pragma unroll
        for (int i = 0; i < 4; i++)
            #pragma unroll
            for (int j = 0; j < 8; j++) acc[i][j] = 0.f;

        #pragma unroll 4
        for (int d = 0; d < DIM; d++) {
            float qf[4], kf[8];
            #pragma unroll
            for (int i = 0; i < 4; i++) qf[i] = sQ[(ty + 16 * i) * PADK + d];
            #pragma unroll
            for (int j = 0; j < 8; j++) kf[j] = sK[(tx + 16 * j) * PADK + d];
            #pragma unroll
            for (int i = 0; i < 4; i++)
                #pragma unroll
                for (int j = 0; j < 8; j++)
                    acc[i][j] = fmaf(qf[i], kf[j], acc[i][j]);
        }

        #pragma unroll
        for (int i = 0; i < 4; i++) {
            float mt = -1e30f;
            #pragma unroll
            for (int j = 0; j < 8; j++) {
                acc[i][j] *= scale;
                mt = fmaxf(mt, acc[i][j]);
            }
            // tile row-max across the 16 tx lanes
            #pragma unroll
            for (int off = 8; off; off >>= 1)
                mt = fmaxf(mt, __shfl_xor_sync(0xffffffffu, mt, off, 16));
            float se = 0.f;
            #pragma unroll
            for (int j = 0; j < 8; j++) se += __expf(acc[i][j] - mt);
            #pragma unroll
            for (int off = 8; off; off >>= 1)
                se += __shfl_xor_sync(0xffffffffu, se, off, 16);

            // online merge (replicated across tx lanes -> stays in sync)
            float mo = m_run[i];
            float mn = fmaxf(mo, mt);
            l_run[i] = l_run[i] * __expf(mo - mn) + se * __expf(mt - mn);
            m_run[i] = mn;

            // write raw scaled scores into the attention output region (scratch)
            float* arow = attn + (size_t)(b * SEQ + q0 + ty + 16 * i) * SEQ + k0;
            #pragma unroll
            for (int j = 0; j < 8; j++) arow[tx + 16 * j] = acc[i][j];
        }
    }

    if (tx == 0) {
        #pragma unroll
        for (int i = 0; i < 4; i++) {
            int row = b * SEQ + q0 + ty + 16 * i;
            g_stats[row * 2]     = m_run[i];
            g_stats[row * 2 + 1] = l_run[i];
        }
    }
}

// ---------------------------------------------------------------------------
// Kernel 2: normalize scores -> final attention, accumulate context = P @ V.
// Same block shape; thread owns rows ty+16i (i<4), dcols tx+16j (j<8).
// ---------------------------------------------------------------------------
__global__ void __launch_bounds__(256, 2) k_context(
    const float* __restrict__ V, float* __restrict__ attn,
    float* __restrict__ ctx)
{
    extern __shared__ float sm[];
    float* sV = sm;                  // KT2 * DIM (unpadded; lane stride conflict-free)
    float* sP = sm + KT2 * DIM;      // QT  * PADP

    const int b   = blockIdx.y;
    const int q0  = blockIdx.x * QT;
    const int tid = threadIdx.x;
    const int tx  = tid & 15;
    const int ty  = tid >> 4;

    float m_r[4], il_r[4];
    #pragma unroll
    for (int i = 0; i < 4; i++) {
        int row = b * SEQ + q0 + ty + 16 * i;
        m_r[i]  = g_stats[row * 2];
        il_r[i] = 1.f / g_stats[row * 2 + 1];
    }

    float acc[4][8];
    #pragma unroll
    for (int i = 0; i < 4; i++)
        #pragma unroll
        for (int j = 0; j < 8; j++) acc[i][j] = 0.f;

    for (int k0 = 0; k0 < SEQ; k0 += KT2) {
        __syncthreads();  // protect previous sV/sP reads
        const float* vg = V + ((size_t)b * SEQ + k0) * DIM;
        for (int idx = tid * 4; idx < KT2 * DIM; idx += 1024)
            *reinterpret_cast<float4*>(sV + idx) =
                *reinterpret_cast<const float4*>(vg + idx);

        // normalize this 64x64 score tile; write final attention + smem P
        #pragma unroll
        for (int i = 0; i < 4; i++) {
            int r = ty + 16 * i;
            float* arow = attn + (size_t)(b * SEQ + q0 + r) * SEQ + k0;
            #pragma unroll
            for (int jj = 0; jj < 4; jj++) {
                int c = tx + 16 * jj;
                float p = __expf(arow[c] - m_r[i]) * il_r[i];
                arow[c] = p;                 // final attention output
                sP[r * PADP + c] = p;
            }
        }
        __syncthreads();

        #pragma unroll 2
        for (int c = 0; c < KT2; c++) {
            float pf[4], vf[8];
            #pragma unroll
            for (int i = 0; i < 4; i++) pf[i] = sP[(ty + 16 * i) * PADP + c];
            #pragma unroll
            for (int j = 0; j < 8; j++) vf[j] = sV[c * DIM + tx + 16 * j];
            #pragma unroll
            for (int i = 0; i < 4; i++)
                #pragma unroll
                for (int j = 0; j < 8; j++)
                    acc[i][j] = fmaf(pf[i], vf[j], acc[i][j]);
        }
    }

    #pragma unroll
    for (int i = 0; i < 4; i++) {
        float* crow = ctx + (size_t)(b * SEQ + q0 + ty + 16 * i) * DIM;
        #pragma unroll
        for (int j = 0; j < 8; j++) crow[tx + 16 * j] = acc[i][j];
    }
}

// ---------------------------------------------------------------------------
extern "C" void kernel_launch(void* const* d_in, const int* in_sizes, int n_in,
                              void* d_out, int out_size)
{
    const float* q = (const float*)d_in[0];
    const float* k = (const float*)d_in[1];
    const float* v = (const float*)d_in[2];

    const int B = in_sizes[0] / (SEQ * DIM);   // 32

    float* ctx  = (float*)d_out;                         // [B, S, D]  (tuple elem 0)
    float* attn = (float*)d_out + (size_t)B * SEQ * DIM; // [B, S, S]  (tuple elem 1)

    const int smem1 = (QT * PADK + KT1 * PADK) * (int)sizeof(float);  // 99072 B
    const int smem2 = (KT2 * DIM + QT * PADP) * (int)sizeof(float);   // 49408 B

    // Attribute setting is idempotent host state, not a stream op: capture-safe.
    cudaFuncSetAttribute(k_scores,  cudaFuncAttributeMaxDynamicSharedMemorySize, smem1);
    cudaFuncSetAttribute(k_context, cudaFuncAttributeMaxDynamicSharedMemorySize, smem2);

    dim3 grid(SEQ / QT, B);   // (32, 32) = 1024 blocks
    k_scores <<<grid, 256, smem1>>>(q, k, attn);
    k_context<<<grid, 256, smem2>>>(v, attn, ctx);
}

// round 12
// speedup vs baseline: 1.5075x; 1.5075x over previous
#include <cuda_runtime.h>
#include <cuda_bf16.h>
#include <stdint.h>

#define SEQ 2048
#define DIM 128
#define MT  128          // q rows per CTA
#define NT  128          // keys per tile
#define NTILES (SEQ / NT)
#define RS  136          // smem bf16 row stride (padding: conflict-free ldmatrix)

#define TILE_B   (MT * RS * 2)        // 34816 bytes per bf16 tile
#define OFF_AHI  0
#define OFF_ALO  (TILE_B)
#define OFF_BHI  (2 * TILE_B)
#define OFF_BLO  (3 * TILE_B)
#define OFF_SM   (4 * TILE_B)         // 139264: statm[128]
#define OFF_SL   (OFF_SM + 512)       // statl[128]
#define OFF_BM   (OFF_SL + 512)       // new-max broadcast[128]
#define OFF_RED  (OFF_BM + 512)       // red[4][128]
#define SMEM1    (OFF_RED + 2048)     // 142848
#define SMEM2    (OFF_BM)             // k2 needs tiles + statm/statl only

#define MAXB 32
__device__ float g_stats[MAXB * SEQ * 2];   // per row: {m, 1/l}

// ---------------------------------------------------------------------------
__device__ __forceinline__ uint32_t smem_u32(const void* p) {
    uint32_t a;
    asm("{ .reg .u64 t; cvta.to.shared.u64 t, %1; cvt.u32.u64 %0, t; }" : "=r"(a) : "l"(p));
    return a;
}

__device__ __forceinline__ void ldsm4(uint32_t* r, uint32_t addr) {
    asm volatile("ldmatrix.sync.aligned.m8n8.x4.shared.b16 {%0,%1,%2,%3}, [%4];"
        : "=r"(r[0]), "=r"(r[1]), "=r"(r[2]), "=r"(r[3]) : "r"(addr));
}
__device__ __forceinline__ void ldsm4t(uint32_t* r, uint32_t addr) {
    asm volatile("ldmatrix.sync.aligned.m8n8.x4.trans.shared.b16 {%0,%1,%2,%3}, [%4];"
        : "=r"(r[0]), "=r"(r[1]), "=r"(r[2]), "=r"(r[3]) : "r"(addr));
}
__device__ __forceinline__ void mma16816(float* c, const uint32_t* a,
                                         uint32_t b0, uint32_t b1) {
    asm volatile(
        "mma.sync.aligned.m16n8k16.row.col.f32.bf16.bf16.f32 "
        "{%0,%1,%2,%3}, {%4,%5,%6,%7}, {%8,%9}, {%0,%1,%2,%3};"
        : "+f"(c[0]), "+f"(c[1]), "+f"(c[2]), "+f"(c[3])
        : "r"(a[0]), "r"(a[1]), "r"(a[2]), "r"(a[3]), "r"(b0), "r"(b1));
}

// split f32 pair into bf16 hi/lo pairs at element offset eoff (even)
__device__ __forceinline__ void split2(char* hi, char* lo, int eoff,
                                       float f0, float f1) {
    __nv_bfloat16 h0 = __float2bfloat16(f0);
    __nv_bfloat16 h1 = __float2bfloat16(f1);
    __nv_bfloat162 hp; hp.x = h0; hp.y = h1;
    __nv_bfloat162 lp;
    lp.x = __float2bfloat16(f0 - __bfloat162float(h0));
    lp.y = __float2bfloat16(f1 - __bfloat162float(h1));
    *reinterpret_cast<__nv_bfloat162*>(hi + 2 * eoff) = hp;
    *reinterpret_cast<__nv_bfloat162*>(lo + 2 * eoff) = lp;
}

// ===========================================================================
// Kernel 1: raw scaled scores (HMMA, 3-term split) + online softmax stats
// 512 threads = 16 warps in a 4(m) x 4(n) grid of 32x32 warp tiles.
// ===========================================================================
__global__ void __launch_bounds__(512, 1) k1_scores(
    const float* __restrict__ Q, const float* __restrict__ K,
    float* __restrict__ attn)
{
    extern __shared__ char sm[];
    const uint32_t sb = smem_u32(sm);
    char* AHI = sm + OFF_AHI; char* ALO = sm + OFF_ALO;
    char* BHI = sm + OFF_BHI; char* BLO = sm + OFF_BLO;
    float* statm = (float*)(sm + OFF_SM);
    float* statl = (float*)(sm + OFF_SL);
    float* bm    = (float*)(sm + OFF_BM);
    float* red   = (float*)(sm + OFF_RED);

    const int tid  = threadIdx.x;
    const int lane = tid & 31;
    const int w    = tid >> 5;
    const int wm   = w >> 2, wn = w & 3;
    const int b    = blockIdx.y;
    const int q0   = blockIdx.x * MT;
    const float scale = 0.08838834764831845f;   // 1/sqrt(128)

    // ldmatrix per-lane element offsets
    const int aoff = (lane & 15) * RS + ((lane & 16) >> 1);                  // A
    const int boff = ((lane & 7) + ((lane & 16) >> 1)) * RS + (lane & 8);    // B (K-tile)

    // Q tile -> scaled bf16 hi/lo
    const float* Qg = Q + ((size_t)b * SEQ + q0) * DIM;
    for (int pi = tid; pi < MT * DIM / 2; pi += 512) {
        int r = pi >> 6, c2 = (pi & 63) * 2;
        float2 f = *(const float2*)(Qg + r * DIM + c2);
        split2(AHI, ALO, r * RS + c2, f.x * scale, f.y * scale);
    }
    if (tid < MT) { statm[tid] = -1e30f; statl[tid] = 0.f; }

    float* attnBase = attn + ((size_t)b * SEQ + q0) * SEQ;
    const float* Kg = K + (size_t)b * SEQ * DIM;

    for (int t = 0; t < NTILES; t++) {
        const int k0 = t * NT;
        __syncthreads();                       // B smem + stats reuse
        for (int pi = tid; pi < NT * DIM / 2; pi += 512) {
            int r = pi >> 6, c2 = (pi & 63) * 2;
            float2 f = *(const float2*)(Kg + (size_t)(k0 + r) * DIM + c2);
            split2(BHI, BLO, r * RS + c2, f.x, f.y);
        }
        __syncthreads();

        float c[2][4][4];
        #pragma unroll
        for (int mi = 0; mi < 2; mi++)
            #pragma unroll
            for (int ni = 0; ni < 4; ni++)
                #pragma unroll
                for (int j = 0; j < 4; j++) c[mi][ni][j] = 0.f;

        #pragma unroll
        for (int ks = 0; ks < 8; ks++) {
            const int k = ks * 16;
            uint32_t qh[2][4], ql[2][4], kh[2][4], kl[2][4];
            #pragma unroll
            for (int mi = 0; mi < 2; mi++) {
                int e = (wm * 32 + mi * 16) * RS + k + aoff;
                ldsm4(qh[mi], sb + OFF_AHI + 2 * e);
                ldsm4(ql[mi], sb + OFF_ALO + 2 * e);
            }
            #pragma unroll
            for (int g = 0; g < 2; g++) {
                int e = (wn * 32 + g * 16) * RS + k + boff;
                ldsm4(kh[g], sb + OFF_BHI + 2 * e);
                ldsm4(kl[g], sb + OFF_BLO + 2 * e);
            }
            #pragma unroll
            for (int mi = 0; mi < 2; mi++)
                #pragma unroll
                for (int ni = 0; ni < 4; ni++) {
                    int g = ni >> 1, ix = (ni & 1) * 2;
                    mma16816(c[mi][ni], qh[mi], kh[g][ix], kh[g][ix + 1]);
                    mma16816(c[mi][ni], qh[mi], kl[g][ix], kl[g][ix + 1]);
                    mma16816(c[mi][ni], ql[mi], kh[g][ix], kh[g][ix + 1]);
                }
        }

        // ---- epilogue: store raw scores + stats ----
        const int t4 = lane >> 2, q4 = lane & 3;
        #pragma unroll
        for (int mi = 0; mi < 2; mi++) {
            int rA = wm * 32 + mi * 16 + t4;
            float mA = -1e30f, mB = -1e30f;
            #pragma unroll
            for (int ni = 0; ni < 4; ni++) {
                int col = k0 + wn * 32 + ni * 8 + 2 * q4;
                *(float2*)(attnBase + (size_t)rA * SEQ + col) =
                    make_float2(c[mi][ni][0], c[mi][ni][1]);
                *(float2*)(attnBase + (size_t)(rA + 8) * SEQ + col) =
                    make_float2(c[mi][ni][2], c[mi][ni][3]);
                mA = fmaxf(mA, fmaxf(c[mi][ni][0], c[mi][ni][1]));
                mB = fmaxf(mB, fmaxf(c[mi][ni][2], c[mi][ni][3]));
            }
            mA = fmaxf(mA, __shfl_xor_sync(0xffffffffu, mA, 1));
            mA = fmaxf(mA, __shfl_xor_sync(0xffffffffu, mA, 2));
            mB = fmaxf(mB, __shfl_xor_sync(0xffffffffu, mB, 1));
            mB = fmaxf(mB, __shfl_xor_sync(0xffffffffu, mB, 2));
            if (q4 == 0) { red[wn * 128 + rA] = mA; red[wn * 128 + rA + 8] = mB; }
        }
        __syncthreads();
        if (tid < MT) {
            float mt = fmaxf(fmaxf(red[tid], red[128 + tid]),
                             fmaxf(red[256 + tid], red[384 + tid]));
            bm[tid] = fmaxf(statm[tid], mt);
        }
        __syncthreads();
        #pragma unroll
        for (int mi = 0; mi < 2; mi++) {
            int rA = wm * 32 + mi * 16 + t4;
            float mA = bm[rA], mB = bm[rA + 8];
            float sA = 0.f, sB = 0.f;
            #pragma unroll
            for (int ni = 0; ni < 4; ni++) {
                sA += __expf(c[mi][ni][0] - mA) + __expf(c[mi][ni][1] - mA);
                sB += __expf(c[mi][ni][2] - mB) + __expf(c[mi][ni][3] - mB);
            }
            sA += __shfl_xor_sync(0xffffffffu, sA, 1);
            sA += __shfl_xor_sync(0xffffffffu, sA, 2);
            sB += __shfl_xor_sync(0xffffffffu, sB, 1);
            sB += __shfl_xor_sync(0xffffffffu, sB, 2);
            if (q4 == 0) { red[wn * 128 + rA] = sA; red[wn * 128 + rA + 8] = sB; }
        }
        __syncthreads();
        if (tid < MT) {
            float mold = statm[tid], mnew = bm[tid];
            float s = red[tid] + red[128 + tid] + red[256 + tid] + red[384 + tid];
            statl[tid] = statl[tid] * __expf(mold - mnew) + s;
            statm[tid] = mnew;
        }
    }

    __syncthreads();
    if (tid < MT) {
        int row = b * SEQ + q0 + tid;
        g_stats[row * 2]     = statm[tid];
        g_stats[row * 2 + 1] = 1.f / statl[tid];
    }
}

// ===========================================================================
// Kernel 2: normalize scores -> final attention; ctx = P @ V (HMMA split)
// ===========================================================================
__global__ void __launch_bounds__(512, 1) k2_context(
    const float* __restrict__ V, float* __restrict__ attn,
    float* __restrict__ ctx)
{
    extern __shared__ char sm[];
    const uint32_t sb = smem_u32(sm);
    char* PHI = sm + OFF_AHI; char* PLO = sm + OFF_ALO;
    char* VHI = sm + OFF_BHI; char* VLO = sm + OFF_BLO;
    float* statm = (float*)(sm + OFF_SM);
    float* statl = (float*)(sm + OFF_SL);

    const int tid  = threadIdx.x;
    const int lane = tid & 31;
    const int w    = tid >> 5;
    const int wm   = w >> 2, wn = w & 3;
    const int b    = blockIdx.y;
    const int q0   = blockIdx.x * MT;

    const int aoff = (lane & 15) * RS + ((lane & 16) >> 1);                 // A (P)
    const int toff = ((lane & 7) + (lane & 8)) * RS + ((lane & 16) >> 1);   // B trans (V)

    if (tid < MT) {
        int row = b * SEQ + q0 + tid;
        statm[tid] = g_stats[row * 2];
        statl[tid] = g_stats[row * 2 + 1];
    }

    float* attnBase = attn + ((size_t)b * SEQ + q0) * SEQ;
    const float* Vg = V + (size_t)b * SEQ * DIM;

    float c[2][4][4];
    #pragma unroll
    for (int mi = 0; mi < 2; mi++)
        #pragma unroll
        for (int ni = 0; ni < 4; ni++)
            #pragma unroll
            for (int j = 0; j < 4; j++) c[mi][ni][j] = 0.f;

    for (int t = 0; t < NTILES; t++) {
        const int k0 = t * NT;
        __syncthreads();                       // smem tile reuse (+ stats visible)
        // normalize P: raw -> prob (final attn output) + split smem
        for (int pi = tid; pi < MT * NT / 2; pi += 512) {
            int r = pi >> 6, c2 = (pi & 63) * 2;
            float* ap = attnBase + (size_t)r * SEQ + k0 + c2;
            float2 s = *(const float2*)ap;
            float m = statm[r], il = statl[r];
            float p0 = __expf(s.x - m) * il;
            float p1 = __expf(s.y - m) * il;
            *(float2*)ap = make_float2(p0, p1);
            split2(PHI, PLO, r * RS + c2, p0, p1);
        }
        // V tile [key][d] -> bf16 hi/lo
        for (int pi = tid; pi < NT * DIM / 2; pi += 512) {
            int r = pi >> 6, c2 = (pi & 63) * 2;
            float2 f = *(const float2*)(Vg + (size_t)(k0 + r) * DIM + c2);
            split2(VHI, VLO, r * RS + c2, f.x, f.y);
        }
        __syncthreads();

        #pragma unroll
        for (int ks = 0; ks < 8; ks++) {
            const int k = ks * 16;
            uint32_t ph[2][4], pl[2][4], vh[2][4], vl[2][4];
            #pragma unroll
            for (int mi = 0; mi < 2; mi++) {
                int e = (wm * 32 + mi * 16) * RS + k + aoff;
                ldsm4(ph[mi], sb + OFF_AHI + 2 * e);
                ldsm4(pl[mi], sb + OFF_ALO + 2 * e);
            }
            #pragma unroll
            for (int g = 0; g < 2; g++) {
                int e = k * RS + (wn * 32 + g * 16) + toff;
                ldsm4t(vh[g], sb + OFF_BHI + 2 * e);
                ldsm4t(vl[g], sb + OFF_BLO + 2 * e);
            }
            #pragma unroll
            for (int mi = 0; mi < 2; mi++)
                #pragma unroll
                for (int ni = 0; ni < 4; ni++) {
                    int g = ni >> 1, ix = (ni & 1) * 2;
                    mma16816(c[mi][ni], ph[mi], vh[g][ix], vh[g][ix + 1]);
                    mma16816(c[mi][ni], ph[mi], vl[g][ix], vl[g][ix + 1]);
                    mma16816(c[mi][ni], pl[mi], vh[g][ix], vh[g][ix + 1]);
                }
        }
    }

    // ctx store straight from fragments (8B/thread, 32B per quad-row)
    float* ctxBase = ctx + ((size_t)b * SEQ + q0) * DIM;
    const int t4 = lane >> 2, q4 = lane & 3;
    #pragma unroll
    for (int mi = 0; mi < 2; mi++) {
        int rA = wm * 32 + mi * 16 + t4;
        #pragma unroll
        for (int ni = 0; ni < 4; ni++) {
            int col = wn * 32 + ni * 8 + 2 * q4;
            *(float2*)(ctxBase + (size_t)rA * DIM + col) =
                make_float2(c[mi][ni][0], c[mi][ni][1]);
            *(float2*)(ctxBase + (size_t)(rA + 8) * DIM + col) =
                make_float2(c[mi][ni][2], c[mi][ni][3]);
        }
    }
}

// ---------------------------------------------------------------------------
extern "C" void kernel_launch(void* const* d_in, const int* in_sizes, int n_in,
                              void* d_out, int out_size)
{
    const float* q = (const float*)d_in[0];
    const float* k = (const float*)d_in[1];
    const float* v = (const float*)d_in[2];

    const int B = in_sizes[0] / (SEQ * DIM);   // 32

    float* ctx  = (float*)d_out;                          // [B, S, D]
    float* attn = (float*)d_out + (size_t)B * SEQ * DIM;  // [B, S, S]

    cudaFuncSetAttribute(k1_scores,  cudaFuncAttributeMaxDynamicSharedMemorySize, SMEM1);
    cudaFuncSetAttribute(k2_context, cudaFuncAttributeMaxDynamicSharedMemorySize, SMEM2);

    dim3 grid(SEQ / MT, B);   // (16, 32) = 512 CTAs
    k1_scores <<<grid, 512, SMEM1>>>(q, k, attn);
    k2_context<<<grid, 512, SMEM2>>>(v, attn, ctx);
}